// round 1
// baseline (speedup 1.0000x reference)
#include <cuda_runtime.h>
#include <math.h>

// Problem dims (fixed by the dataset).
#define BATCH 1024
#define NIN   512
#define NHID  256

// ---------------------------------------------------------------------------
// Scratch in __device__ globals (no allocation allowed in kernel_launch).
// ---------------------------------------------------------------------------
__device__ int          g_sel1[NHID];                 // 1 = max-node, 0 = min-node
__device__ int          g_sel2[NIN];
__device__ unsigned int g_mb1[NHID * (NIN  / 32)];    // [256][16] bit-packed mask1
__device__ unsigned int g_mb2[NIN  * (NHID / 32)];    // [512][8]  bit-packed mask2
__device__ float        g_h[NHID * BATCH];            // layer-1 out, TRANSPOSED [h][b]

// ---------------------------------------------------------------------------
// Gumbel hard-select: forward value is exactly the one-hot of argmax(logits+g).
// ---------------------------------------------------------------------------
__device__ __forceinline__ float gumbel_f(float u) {
    u = fminf(fmaxf(u, 1e-10f), 1.0f);
    return -logf(-logf(u));
}

__global__ void prep_sel_kernel(const float* __restrict__ logits1,
                                const float* __restrict__ u1,
                                const float* __restrict__ logits2,
                                const float* __restrict__ u2) {
    int t = threadIdx.x;
    if (t < NHID) {
        float z0 = logits1[2 * t]     + gumbel_f(u1[2 * t]);
        float z1 = logits1[2 * t + 1] + gumbel_f(u1[2 * t + 1]);
        g_sel1[t] = (z1 > z0) ? 1 : 0;   // argmax: index 1 only on strict >
    }
    if (t < NIN) {
        float z0 = logits2[2 * t]     + gumbel_f(u2[2 * t]);
        float z1 = logits2[2 * t + 1] + gumbel_f(u2[2 * t + 1]);
        g_sel2[t] = (z1 > z0) ? 1 : 0;
    }
}

// ---------------------------------------------------------------------------
// Mask dtype detection (harness may hand us bool(1B), int32, or float32).
// Pattern-probe the first 64 words: int32 0/1 -> mode 2, f32 0.0/1.0 -> mode 3,
// otherwise bytes -> mode 1. False-positive probability is ~2^-144.
// ---------------------------------------------------------------------------
__device__ int detect_mode(const void* p) {
    const unsigned int* pw = (const unsigned int*)p;
    bool i32ok = true, f32ok = true;
    for (int g = 0; g < 64; g++) {
        unsigned int v = pw[g];
        i32ok = i32ok && (v == 0u || v == 1u);
        f32ok = f32ok && (v == 0u || v == 0x3F800000u);
    }
    return i32ok ? 2 : (f32ok ? 3 : 1);
}

__device__ __forceinline__ bool mask_at(const void* p, int mode, int e) {
    if (mode == 2) return ((const int*)p)[e] != 0;
    if (mode == 3) return ((const float*)p)[e] != 0.0f;
    return ((const unsigned char*)p)[e] != 0;
}

__global__ void pack_masks_kernel(const void* __restrict__ mask1,
                                  const void* __restrict__ mask2) {
    __shared__ int modes[2];
    if (threadIdx.x == 0) {
        modes[0] = detect_mode(mask1);
        modes[1] = detect_mode(mask2);
    }
    __syncthreads();
    const int W1 = NHID * (NIN / 32);   // 4096 words
    const int W2 = NIN * (NHID / 32);   // 4096 words
    int wid = blockIdx.x * blockDim.x + threadIdx.x;
    if (wid < W1) {
        int base = wid * 32;
        unsigned int bits = 0u;
        #pragma unroll 8
        for (int k = 0; k < 32; k++)
            if (mask_at(mask1, modes[0], base + k)) bits |= (1u << k);
        g_mb1[wid] = bits;
    } else if (wid < W1 + W2) {
        int w2 = wid - W1;
        int base = w2 * 32;
        unsigned int bits = 0u;
        #pragma unroll 8
        for (int k = 0; k < 32; k++)
            if (mask_at(mask2, modes[1], base + k)) bits |= (1u << k);
        g_mb2[w2] = bits;
    }
}

// ---------------------------------------------------------------------------
// Layer 1: x[B][512] -> g_h[h][B]  (transposed write: coalesced)
// Block: 256 threads (8 warps). lane = batch row within a 32-row tile.
// smem tile xs[c][r] padded to 33 floats/column: conflict-free both ways.
// Each warp handles 4 h-nodes; per node: 16 uniform mask words, 32 bits each,
// predicated LDS+FMNMX, 4 accumulators for ILP.
// ---------------------------------------------------------------------------
__global__ void layer1_kernel(const float* __restrict__ x) {
    extern __shared__ float xs[];   // [NIN][33] = 67584 B
    const int lane = threadIdx.x & 31;
    const int warp = threadIdx.x >> 5;
    const int b0 = blockIdx.x * 32;
    const int h0 = blockIdx.y * 32;

    for (int idx = threadIdx.x; idx < 32 * NIN; idx += blockDim.x) {
        int r = idx >> 9;            // 0..31 (batch row in tile)
        int c = idx & (NIN - 1);     // 0..511
        xs[c * 33 + r] = x[(b0 + r) * NIN + c];
    }
    __syncthreads();

    for (int hh = warp; hh < 32; hh += 8) {
        int h = h0 + hh;
        float res;
        if (g_sel1[h]) {
            float a[4] = {0.0f, 0.0f, 0.0f, 0.0f};
            for (int w = 0; w < 16; w++) {
                unsigned int m = g_mb1[h * 16 + w];
                const float* p = &xs[(w * 32) * 33 + lane];
                #pragma unroll
                for (int k = 0; k < 32; k++)
                    if (m & (1u << k)) a[k & 3] = fmaxf(a[k & 3], p[k * 33]);
            }
            res = fmaxf(fmaxf(a[0], a[1]), fmaxf(a[2], a[3]));
        } else {
            float a[4] = {1.0f, 1.0f, 1.0f, 1.0f};
            for (int w = 0; w < 16; w++) {
                unsigned int m = g_mb1[h * 16 + w];
                const float* p = &xs[(w * 32) * 33 + lane];
                #pragma unroll
                for (int k = 0; k < 32; k++)
                    if (m & (1u << k)) a[k & 3] = fminf(a[k & 3], p[k * 33]);
            }
            res = fminf(fminf(a[0], a[1]), fminf(a[2], a[3]));
        }
        res = fmaxf(res, 0.0f);   // max(sel*values) semantics (other term is exactly 0)
        g_h[h * BATCH + b0 + lane] = res;
    }
}

// ---------------------------------------------------------------------------
// Layer 2: g_h[h][B] -> out[B][512]. Output staged through smem so the final
// global write is coalesced.
// ---------------------------------------------------------------------------
__global__ void layer2_kernel(float* __restrict__ out) {
    extern __shared__ float smem[];
    float* hs   = smem;               // [NHID][33] = 8448 floats
    float* outs = smem + NHID * 33;   // [64][33]   = 2112 floats
    const int lane = threadIdx.x & 31;
    const int warp = threadIdx.x >> 5;
    const int b0 = blockIdx.x * 32;
    const int j0 = blockIdx.y * 64;

    for (int idx = threadIdx.x; idx < 32 * NHID; idx += blockDim.x) {
        int c = idx >> 5;            // 0..255 (hid index)
        int r = idx & 31;            // 0..31  (batch row)
        hs[c * 33 + r] = g_h[c * BATCH + b0 + r];
    }
    __syncthreads();

    for (int jj = warp; jj < 64; jj += 8) {
        int j = j0 + jj;
        float res;
        if (g_sel2[j]) {
            float a[4] = {0.0f, 0.0f, 0.0f, 0.0f};
            for (int w = 0; w < 8; w++) {
                unsigned int m = g_mb2[j * 8 + w];
                const float* p = &hs[(w * 32) * 33 + lane];
                #pragma unroll
                for (int k = 0; k < 32; k++)
                    if (m & (1u << k)) a[k & 3] = fmaxf(a[k & 3], p[k * 33]);
            }
            res = fmaxf(fmaxf(a[0], a[1]), fmaxf(a[2], a[3]));
        } else {
            float a[4] = {1.0f, 1.0f, 1.0f, 1.0f};
            for (int w = 0; w < 8; w++) {
                unsigned int m = g_mb2[j * 8 + w];
                const float* p = &hs[(w * 32) * 33 + lane];
                #pragma unroll
                for (int k = 0; k < 32; k++)
                    if (m & (1u << k)) a[k & 3] = fminf(a[k & 3], p[k * 33]);
            }
            res = fminf(fminf(a[0], a[1]), fminf(a[2], a[3]));
        }
        res = fmaxf(res, 0.0f);
        outs[jj * 33 + lane] = res;
    }
    __syncthreads();

    for (int idx = threadIdx.x; idx < 32 * 64; idx += blockDim.x) {
        int r = idx >> 6;            // 0..31
        int c = idx & 63;            // 0..63
        out[(b0 + r) * NIN + j0 + c] = outs[c * 33 + r];
    }
}

// ---------------------------------------------------------------------------
// kernel_launch: prep (sel + mask bitpack) -> layer1 -> layer2.
// All launches on the default stream; graph-capturable; no allocation.
// ---------------------------------------------------------------------------
extern "C" void kernel_launch(void* const* d_in, const int* in_sizes, int n_in,
                              void* d_out, int out_size) {
    const float* x       = (const float*)d_in[0];
    const float* logits1 = (const float*)d_in[1];
    const float* u1      = (const float*)d_in[2];
    const float* logits2 = (const float*)d_in[3];
    const float* u2      = (const float*)d_in[4];
    const void*  mask1   = d_in[5];
    const void*  mask2   = d_in[6];
    float* out = (float*)d_out;

    (void)in_sizes; (void)n_in; (void)out_size;

    const int smem1 = NIN * 33 * (int)sizeof(float);                 // 67584 B
    const int smem2 = (NHID * 33 + 64 * 33) * (int)sizeof(float);    // 42240 B
    cudaFuncSetAttribute(layer1_kernel, cudaFuncAttributeMaxDynamicSharedMemorySize, smem1);
    cudaFuncSetAttribute(layer2_kernel, cudaFuncAttributeMaxDynamicSharedMemorySize, smem2);

    prep_sel_kernel<<<1, 512>>>(logits1, u1, logits2, u2);
    pack_masks_kernel<<<32, 256>>>(mask1, mask2);
    layer1_kernel<<<dim3(BATCH / 32, NHID / 32), 256, smem1>>>(x);
    layer2_kernel<<<dim3(BATCH / 32, NIN / 64), 256, smem2>>>(out);
}

// round 2
// speedup vs baseline: 1.3816x; 1.3816x over previous
#include <cuda_runtime.h>
#include <math.h>

#define BATCH 1024
#define NIN   512
#define NHID  256

// ---------------------------------------------------------------------------
// Device-global scratch (no allocation allowed anywhere).
// ---------------------------------------------------------------------------
__device__ int      g_sel1[NHID];            // 1 = max-node, 0 = min-node
__device__ int      g_sel2[NIN];
__device__ int      g_mode[2];               // mask dtype mode per input
__device__ unsigned g_mT1[16 * NHID];        // transposed bitmask [w][node], layer1
__device__ unsigned g_mT2[8 * NIN];          // transposed bitmask [w][node], layer2
__device__ float    g_h[BATCH * NHID];       // layer-1 output, row-major [b][h]

// ---------------------------------------------------------------------------
// Gumbel hard-select: forward value is exactly one-hot of argmax(logits + g).
// ---------------------------------------------------------------------------
__device__ __forceinline__ float gumbel_f(float u) {
    u = fminf(fmaxf(u, 1e-10f), 1.0f);
    return -logf(-logf(u));
}

// Mask dtype detection (bool 1B / int32 / float32) — probe 64 words.
__device__ int detect_mode(const void* p) {
    const unsigned* pw = (const unsigned*)p;
    bool i32ok = true, f32ok = true;
    for (int g = 0; g < 64; g++) {
        unsigned v = pw[g];
        i32ok = i32ok && (v == 0u || v == 1u);
        f32ok = f32ok && (v == 0u || v == 0x3F800000u);
    }
    return i32ok ? 2 : (f32ok ? 3 : 1);
}

__device__ __forceinline__ bool mask_at(const void* p, int mode, int e) {
    if (mode == 2) return ((const int*)p)[e] != 0;
    if (mode == 3) return ((const float*)p)[e] != 0.0f;
    return ((const unsigned char*)p)[e] != 0;
}

__global__ void prep_sel_kernel(const float* __restrict__ logits1,
                                const float* __restrict__ u1,
                                const float* __restrict__ logits2,
                                const float* __restrict__ u2,
                                const void* __restrict__ mask1,
                                const void* __restrict__ mask2) {
    int t = threadIdx.x;
    if (t == 0) g_mode[0] = detect_mode(mask1);
    if (t == 1) g_mode[1] = detect_mode(mask2);
    if (t < NHID) {
        float z0 = logits1[2 * t]     + gumbel_f(u1[2 * t]);
        float z1 = logits1[2 * t + 1] + gumbel_f(u1[2 * t + 1]);
        g_sel1[t] = (z1 > z0) ? 1 : 0;   // argmax: ties -> index 0
    }
    if (t < NIN) {
        float z0 = logits2[2 * t]     + gumbel_f(u2[2 * t]);
        float z1 = logits2[2 * t + 1] + gumbel_f(u2[2 * t + 1]);
        g_sel2[t] = (z1 > z0) ? 1 : 0;
    }
}

// Transposed bit-packed masks: g_mT[w][node], bit b of word w = mask[node][w*32+b].
// One warp per node; ballot builds each word.
__global__ void prep_masks_kernel(const void* __restrict__ m1,
                                  const void* __restrict__ m2) {
    int gw   = (blockIdx.x * blockDim.x + threadIdx.x) >> 5;
    int lane = threadIdx.x & 31;
    if (gw < NHID) {
        int node = gw, mode = g_mode[0];
        for (int w = 0; w < 16; w++) {
            bool b = mask_at(m1, mode, node * NIN + w * 32 + lane);
            unsigned bits = __ballot_sync(0xffffffffu, b);
            if (lane == 0) g_mT1[w * NHID + node] = bits;
        }
    } else if (gw < NHID + NIN) {
        int node = gw - NHID, mode = g_mode[1];
        for (int w = 0; w < 8; w++) {
            bool b = mask_at(m2, mode, node * NHID + w * 32 + lane);
            unsigned bits = __ballot_sync(0xffffffffu, b);
            if (lane == 0) g_mT2[w * NIN + node] = bits;
        }
    }
}

// ---------------------------------------------------------------------------
// Warp bitonic sort of 32*R u32 keys, ascending. Element i = lane*R + r.
// In-register compare-exchanges for distance < R, shfl.bfly for >= R.
// ---------------------------------------------------------------------------
template<int R, int J>
__device__ __forceinline__ void inreg_pass(unsigned* key, int lane, int k) {
    if (2 * J > k) return;   // this pass only exists when j = J < k
    #pragma unroll
    for (int r = 0; r < R; r++) {
        if ((r & J) == 0) {
            bool asc = (((unsigned)(lane * R + r) & (unsigned)k) == 0);
            unsigned a = key[r], b = key[r + J];
            unsigned mn = a < b ? a : b;
            unsigned mx = a < b ? b : a;
            key[r]     = asc ? mn : mx;
            key[r + J] = asc ? mx : mn;
        }
    }
}

template<int R>
__device__ __forceinline__ void bitonic_sort_warp(unsigned* key) {
    const int lane = threadIdx.x & 31;
    const int N = 32 * R;
    for (int k = 2; k <= N; k <<= 1) {
        // cross-lane passes: j = m*R, partner lane = lane ^ m
        for (int m = (k >> 1) / R; m >= 1; m >>= 1) {
            #pragma unroll
            for (int r = 0; r < R; r++) {
                unsigned a = key[r];
                unsigned b = __shfl_xor_sync(0xffffffffu, a, m);
                bool asc   = (((unsigned)(lane * R + r) & (unsigned)k) == 0);
                bool lower = ((lane & m) == 0);
                unsigned mn = a < b ? a : b;
                unsigned mx = a < b ? b : a;
                key[r] = (lower == asc) ? mn : mx;
            }
        }
        // in-register tail: j = R/2 .. 1 (guarded by j < k inside)
        if (R >= 16) inreg_pass<R, 8>(key, lane, k);
        if (R >= 8)  inreg_pass<R, 4>(key, lane, k);
        inreg_pass<R, 2>(key, lane, k);
        inreg_pass<R, 1>(key, lane, k);
    }
}

// ---------------------------------------------------------------------------
// Layer kernel: one warp per batch row. Sort the row once (keys carry the
// element index in the low bits), then per node walk the sorted list from the
// sel-dependent end until the first active element. Exact value re-read by idx.
// ---------------------------------------------------------------------------
template<int N, int NNODES, int LAYER>
__global__ void __launch_bounds__(128) layer_kernel(const float* __restrict__ in_arg,
                                                    float* __restrict__ out_arg) {
    constexpr int R  = N / 32;     // keys per lane
    constexpr int MW = N / 32;     // mask words per node
    __shared__ unsigned s_mask[MW * NNODES];   // 4096 words = 16KB (both layers)
    __shared__ unsigned s_keys[4][N];
    __shared__ float    s_vals[4][N];

    const int lane = threadIdx.x & 31;
    const int warp = threadIdx.x >> 5;
    const int row  = blockIdx.x * 4 + warp;

    const float* in  = (LAYER == 1) ? in_arg : g_h;
    float*       op  = (LAYER == 1) ? g_h    : out_arg;
    const unsigned* mg = (LAYER == 1) ? g_mT1 : g_mT2;
    const int*     selp = (LAYER == 1) ? g_sel1 : g_sel2;

    // cooperative transposed-mask copy into smem (conflict-free in walks:
    // addr = w*NNODES + node, NNODES multiple of 32 -> bank == lane)
    {
        const uint4* mg4 = (const uint4*)mg;
        uint4* sm4 = (uint4*)s_mask;
        #pragma unroll
        for (int i = threadIdx.x; i < (MW * NNODES) / 4; i += 128) sm4[i] = mg4[i];
    }

    // load my row, stash exact values, build sortable keys
    unsigned key[R];
    #pragma unroll
    for (int rr = 0; rr < R; rr += 4) {
        float4 v = *(const float4*)(in + (size_t)row * N + lane * R + rr);
        float vv[4] = {v.x, v.y, v.z, v.w};
        #pragma unroll
        for (int q = 0; q < 4; q++) {
            int c = lane * R + rr + q;
            s_vals[warp][c] = vv[q];
            key[rr + q] = (__float_as_uint(vv[q]) & ~(unsigned)(N - 1)) | (unsigned)c;
        }
    }

    bitonic_sort_warp<R>(key);

    #pragma unroll
    for (int r = 0; r < R; r++) s_keys[warp][lane * R + r] = key[r];
    __syncthreads();   // masks + keys + vals visible

    // walks: lane = node within a 32-node group
    #pragma unroll 1
    for (int g = 0; g < NNODES / 32; g++) {
        int node = g * 32 + lane;
        int sel  = selp[node];
        unsigned posmask = sel ? (unsigned)(N - 1) : 0u;  // sel: walk descending
        bool found = false;
        int  fidx  = 0;
        int  t = 0;
        while (true) {
            #pragma unroll
            for (int q = 0; q < 2; q++) {
                unsigned kk = s_keys[warp][(t + q) ^ posmask];
                int idx = (int)(kk & (unsigned)(N - 1));
                unsigned mw = s_mask[(idx >> 5) * NNODES + node];
                bool hit = (mw >> (idx & 31)) & 1u;
                if (!found && hit) { found = true; fidx = idx; }
            }
            t += 2;
            if (__all_sync(0xffffffffu, found) || t >= N) break;
        }
        float v = found ? s_vals[warp][fidx] : (sel ? 0.0f : 1.0f);
        op[(size_t)row * NNODES + node] = fmaxf(v, 0.0f);
    }
}

// ---------------------------------------------------------------------------
// kernel_launch: prep(sel+modes) -> mask transpose -> layer1 -> layer2.
// ---------------------------------------------------------------------------
extern "C" void kernel_launch(void* const* d_in, const int* in_sizes, int n_in,
                              void* d_out, int out_size) {
    const float* x       = (const float*)d_in[0];
    const float* logits1 = (const float*)d_in[1];
    const float* u1      = (const float*)d_in[2];
    const float* logits2 = (const float*)d_in[3];
    const float* u2      = (const float*)d_in[4];
    const void*  mask1   = d_in[5];
    const void*  mask2   = d_in[6];
    float* out = (float*)d_out;
    (void)in_sizes; (void)n_in; (void)out_size;

    prep_sel_kernel<<<1, 512>>>(logits1, u1, logits2, u2, mask1, mask2);
    prep_masks_kernel<<<96, 256>>>(mask1, mask2);
    layer_kernel<NIN,  NHID, 1><<<BATCH / 4, 128>>>(x, nullptr);
    layer_kernel<NHID, NIN,  2><<<BATCH / 4, 128>>>(nullptr, out);
}

// round 3
// speedup vs baseline: 1.7964x; 1.3002x over previous
#include <cuda_runtime.h>
#include <math.h>

#define BATCH 1024
#define NIN   512
#define NHID  256

// ---------------------------------------------------------------------------
// Device-global scratch (no allocation allowed anywhere).
// ---------------------------------------------------------------------------
__device__ unsigned g_mT1[16 * NHID];        // transposed bitmask [w][node], layer1
__device__ unsigned g_mT2[8 * NIN];          // transposed bitmask [w][node], layer2
__device__ float    g_h[BATCH * NHID];       // layer-1 output, row-major [b][h]
__device__ unsigned g_sk1[BATCH * NIN];      // sorted keys per row, layer1 input
__device__ unsigned g_sk2[BATCH * NHID];     // sorted keys per row, layer2 input

// ---------------------------------------------------------------------------
// Gumbel hard-select: forward value is exactly one-hot of argmax(logits + g).
// ---------------------------------------------------------------------------
__device__ __forceinline__ float gumbel_f(float u) {
    u = fminf(fmaxf(u, 1e-10f), 1.0f);
    return -logf(-logf(u));
}

// Mask dtype detection (bool 1B / int32 / float32) — probe 64 words.
__device__ int detect_mode(const void* p) {
    const unsigned* pw = (const unsigned*)p;
    bool i32ok = true, f32ok = true;
    #pragma unroll 8
    for (int g = 0; g < 64; g++) {
        unsigned v = pw[g];
        i32ok = i32ok && (v == 0u || v == 1u);
        f32ok = f32ok && (v == 0u || v == 0x3F800000u);
    }
    return i32ok ? 2 : (f32ok ? 3 : 1);
}

__device__ __forceinline__ bool mask_at(const void* p, int mode, int e) {
    if (mode == 2) return ((const int*)p)[e] != 0;
    if (mode == 3) return ((const float*)p)[e] != 0.0f;
    return ((const unsigned char*)p)[e] != 0;
}

// Transposed bit-packed masks: g_mT[w][node]. One warp per node; ballot packs.
// Mask dtype detected per block (cheap, removes a dependent tiny launch).
__global__ void prep_masks_kernel(const void* __restrict__ m1,
                                  const void* __restrict__ m2) {
    __shared__ int modes[2];
    if (threadIdx.x == 0) modes[0] = detect_mode(m1);
    if (threadIdx.x == 32) modes[1] = detect_mode(m2);
    __syncthreads();
    int gw   = (blockIdx.x * blockDim.x + threadIdx.x) >> 5;
    int lane = threadIdx.x & 31;
    if (gw < NHID) {
        int node = gw, mode = modes[0];
        #pragma unroll
        for (int w = 0; w < 16; w++) {
            bool b = mask_at(m1, mode, node * NIN + w * 32 + lane);
            unsigned bits = __ballot_sync(0xffffffffu, b);
            if (lane == 0) g_mT1[w * NHID + node] = bits;
        }
    } else if (gw < NHID + NIN) {
        int node = gw - NHID, mode = modes[1];
        #pragma unroll
        for (int w = 0; w < 8; w++) {
            bool b = mask_at(m2, mode, node * NHID + w * 32 + lane);
            unsigned bits = __ballot_sync(0xffffffffu, b);
            if (lane == 0) g_mT2[w * NIN + node] = bits;
        }
    }
}

// ---------------------------------------------------------------------------
// Warp bitonic sort of 32*R u32 keys, ascending. Element i = lane*R + r.
// ---------------------------------------------------------------------------
template<int R, int J>
__device__ __forceinline__ void inreg_pass(unsigned* key, int lane, int k) {
    if (2 * J > k) return;
    #pragma unroll
    for (int r = 0; r < R; r++) {
        if ((r & J) == 0) {
            bool asc = (((unsigned)(lane * R + r) & (unsigned)k) == 0);
            unsigned a = key[r], b = key[r + J];
            unsigned mn = a < b ? a : b;
            unsigned mx = a < b ? b : a;
            key[r]     = asc ? mn : mx;
            key[r + J] = asc ? mx : mn;
        }
    }
}

template<int R>
__device__ __forceinline__ void bitonic_sort_warp(unsigned* key) {
    const int lane = threadIdx.x & 31;
    const int N = 32 * R;
    for (int k = 2; k <= N; k <<= 1) {
        for (int m = (k >> 1) / R; m >= 1; m >>= 1) {
            #pragma unroll
            for (int r = 0; r < R; r++) {
                unsigned a = key[r];
                unsigned b = __shfl_xor_sync(0xffffffffu, a, m);
                bool asc   = (((unsigned)(lane * R + r) & (unsigned)k) == 0);
                bool lower = ((lane & m) == 0);
                unsigned mn = a < b ? a : b;
                unsigned mx = a < b ? b : a;
                key[r] = (lower == asc) ? mn : mx;
            }
        }
        if (R >= 16) inreg_pass<R, 8>(key, lane, k);
        if (R >= 8)  inreg_pass<R, 4>(key, lane, k);
        inreg_pass<R, 2>(key, lane, k);
        inreg_pass<R, 1>(key, lane, k);
    }
}

// ---------------------------------------------------------------------------
// Sort kernel: one warp per batch row; keys = (value bits with low log2(N)
// bits replaced by element index) -> monotonic for the all-nonnegative inputs.
// ---------------------------------------------------------------------------
template<int N, int LAYER>
__global__ void __launch_bounds__(128) sort_kernel(const float* __restrict__ in_arg) {
    constexpr int R = N / 32;
    const float* in = (LAYER == 1) ? in_arg : g_h;
    unsigned*    kg = (LAYER == 1) ? g_sk1  : g_sk2;
    const int lane = threadIdx.x & 31;
    const int warp = threadIdx.x >> 5;
    const int row  = blockIdx.x * 4 + warp;

    unsigned key[R];
    #pragma unroll
    for (int rr = 0; rr < R; rr += 4) {
        float4 v = *(const float4*)(in + (size_t)row * N + lane * R + rr);
        float vv[4] = {v.x, v.y, v.z, v.w};
        #pragma unroll
        for (int q = 0; q < 4; q++) {
            int c = lane * R + rr + q;
            key[rr + q] = (__float_as_uint(vv[q]) & ~(unsigned)(N - 1)) | (unsigned)c;
        }
    }
    bitonic_sort_warp<R>(key);
    #pragma unroll
    for (int rr = 0; rr < R; rr += 4) {
        uint4 o; o.x = key[rr]; o.y = key[rr + 1]; o.z = key[rr + 2]; o.w = key[rr + 3];
        *(uint4*)(kg + (size_t)row * N + lane * R + rr) = o;
    }
}

// ---------------------------------------------------------------------------
// Walk kernel: block = 4 rows x 128 nodes, 256 threads. Each thread owns a
// (row, node) pair (two pairs, interleaved for MLP) and walks the row's sorted
// key list from the sel-dependent end to the first mask-active element.
// ---------------------------------------------------------------------------
template<int N, int NNODES, int LAYER>
__global__ void __launch_bounds__(256) walk_kernel(const float* __restrict__ in_arg,
                                                   float* __restrict__ out_arg,
                                                   const float* __restrict__ logits,
                                                   const float* __restrict__ uu) {
    constexpr int MW  = N / 32;
    constexpr int NPB = 128;
    constexpr int RPB = 4;
    __shared__ unsigned      s_keys[RPB][N];
    __shared__ float         s_vals[RPB][N];
    __shared__ unsigned      s_mask[MW * NPB];
    __shared__ unsigned char s_sel[NPB];

    const int r0 = blockIdx.x * RPB;
    const int n0 = blockIdx.y * NPB;
    const float*    in = (LAYER == 1) ? in_arg : g_h;
    float*          op = (LAYER == 1) ? g_h    : out_arg;
    const unsigned* mg = (LAYER == 1) ? g_mT1  : g_mT2;
    const unsigned* kg = (LAYER == 1) ? g_sk1  : g_sk2;

    // sel for this block's nodes (recomputed per block: cheaper than a launch)
    if (threadIdx.x < NPB) {
        int node = n0 + threadIdx.x;
        float z0 = logits[2 * node]     + gumbel_f(uu[2 * node]);
        float z1 = logits[2 * node + 1] + gumbel_f(uu[2 * node + 1]);
        s_sel[threadIdx.x] = (z1 > z0) ? 1 : 0;
    }
    // mask slice: s_mask[w][nloc], bank == nloc&31 -> conflict-free in walk
    #pragma unroll
    for (int i = threadIdx.x; i < MW * NPB; i += 256) {
        int w = i >> 7, nl = i & 127;
        s_mask[i] = mg[w * NNODES + n0 + nl];
    }
    // sorted keys + exact values for 4 rows (contiguous -> vectorized)
    {
        const uint4*  kg4 = (const uint4*)(kg + (size_t)r0 * N);
        const float4* in4 = (const float4*)(in + (size_t)r0 * N);
        uint4*  sk4 = (uint4*)&s_keys[0][0];
        float4* sv4 = (float4*)&s_vals[0][0];
        #pragma unroll
        for (int i = threadIdx.x; i < RPB * N / 4; i += 256) {
            sk4[i] = kg4[i];
            sv4[i] = in4[i];
        }
    }
    __syncthreads();

    const int nloc = threadIdx.x & 127;          // warp lanes = consecutive nodes
    const int rA   = threadIdx.x >> 7;           // 0..1
    const int rB   = rA + 2;
    const int node = n0 + nloc;
    const int sel  = s_sel[nloc];
    const unsigned posm = sel ? (unsigned)(N - 1) : 0u;  // max: walk descending

    float vA = sel ? 0.0f : 1.0f, vB = vA;       // empty-mask identities
    bool  fA = false, fB = false;
    for (int t = 0; t < N; t++) {
        unsigned p = (unsigned)t ^ posm;
        if (!fA) {
            unsigned kk = s_keys[rA][p];
            int idx = (int)(kk & (unsigned)(N - 1));
            if ((s_mask[(idx >> 5) * NPB + nloc] >> (idx & 31)) & 1u) {
                vA = s_vals[rA][idx]; fA = true;
            }
        }
        if (!fB) {
            unsigned kk = s_keys[rB][p];
            int idx = (int)(kk & (unsigned)(N - 1));
            if ((s_mask[(idx >> 5) * NPB + nloc] >> (idx & 31)) & 1u) {
                vB = s_vals[rB][idx]; fB = true;
            }
        }
        if (fA && fB) break;
    }
    op[(size_t)(r0 + rA) * NNODES + node] = fmaxf(vA, 0.0f);
    op[(size_t)(r0 + rB) * NNODES + node] = fmaxf(vB, 0.0f);
}

// ---------------------------------------------------------------------------
// kernel_launch: masks -> sort1 -> walk1 -> sort2 -> walk2.
// ---------------------------------------------------------------------------
extern "C" void kernel_launch(void* const* d_in, const int* in_sizes, int n_in,
                              void* d_out, int out_size) {
    const float* x       = (const float*)d_in[0];
    const float* logits1 = (const float*)d_in[1];
    const float* u1      = (const float*)d_in[2];
    const float* logits2 = (const float*)d_in[3];
    const float* u2      = (const float*)d_in[4];
    const void*  mask1   = d_in[5];
    const void*  mask2   = d_in[6];
    float* out = (float*)d_out;
    (void)in_sizes; (void)n_in; (void)out_size;

    prep_masks_kernel<<<96, 256>>>(mask1, mask2);
    sort_kernel<NIN, 1><<<BATCH / 4, 128>>>(x);
    walk_kernel<NIN, NHID, 1><<<dim3(BATCH / 4, NHID / 128), 256>>>(x, nullptr, logits1, u1);
    sort_kernel<NHID, 2><<<BATCH / 4, 128>>>(nullptr);
    walk_kernel<NHID, NIN, 2><<<dim3(BATCH / 4, NIN / 128), 256>>>(nullptr, out, logits2, u2);
}